// round 3
// baseline (speedup 1.0000x reference)
#include <cuda_runtime.h>

// Problem constants
#define DD  48
#define HH  256
#define WW  256
#define DM  48
#define HM  128
#define WM  128
#define PHN 4

// image:  d_in[0]  float32 [1][1][48][256][256][2]  = 6,291,456
// mvf:    d_in[1]  float32 [1][4][3][48][128][128]  = 9,437,184
// out:             float32 [1][5][48][256][256][2]  = 31,457,280

#define COPY_N4  (DD * HH * (WW / 2))          // 1,572,864 float4 (phase-0 copy)
#define WARP_N   (PHN * DD * HH * (WW / 2))    // 6,291,456 work items (2 x-pixels each)

__global__ __launch_bounds__(256) void mvf_fused_kernel(
    const float* __restrict__ image,   // [48][256][256][2]
    const float* __restrict__ mvf,     // [4][3][48][128][128]
    float4* __restrict__ out4)         // [5][48][256][256][2] viewed as float4
{
    int tid = blockIdx.x * blockDim.x + threadIdx.x;

    // ---- First COPY_N4 threads: stream phase-0 (identity copy) ----
    if (tid < COPY_N4) {
        out4[tid] = ((const float4*)image)[tid];
        return;
    }
    tid -= COPY_N4;
    if (tid >= WARP_N) return;

    const int xh = tid & 127;          // x-pair index; output x = 2*xh, 2*xh+1
    const int y  = (tid >> 7) & 255;
    const int zp = tid >> 15;          // p*48 + z  in [0,192)
    const int p  = zp / DD;
    const int z  = zp - p * DD;

    // --- y-axis upsample coords (shared by both x sub-pixels) ---
    float uy = 0.5f * (float)y - 0.25f;
    uy = fminf(fmaxf(uy, 0.0f), (float)(HM - 1));
    const int   jy  = (int)uy;                 // uy >= 0 so trunc == floor
    const float fy  = uy - (float)jy;
    const int   jy1 = min(jy + 1, HM - 1);

    // --- x-axis taps: columns {xh-1, xh, xh+1} clamped; shared middle tap ---
    const int   cA  = max(xh - 1, 0);          // left tap  (sub 0)
    const int   cB  = xh;                      // shared middle tap
    const int   cC  = min(xh + 1, WM - 1);     // right tap (sub 1)
    const float fx0 = (xh == 0)  ? 0.0f : 0.75f;   // sub0: lerp(v[cA], v[cB], fx0)
    const float fx1 = 0.25f;                       // sub1: lerp(v[cB], v[cC], fx1)

    // --- bilinear-upsample the 3 flow components for both sub-pixels ---
    float flow0[3], flow1[3];
    #pragma unroll
    for (int c = 0; c < 3; ++c) {
        const float* __restrict__ m = mvf + (((p * 3 + c) * DM + z) << 14); // *128*128
        const float a0 = __ldg(&m[(jy  << 7) + cA]);
        const float b0 = __ldg(&m[(jy  << 7) + cB]);
        const float c0 = __ldg(&m[(jy  << 7) + cC]);
        const float a1 = __ldg(&m[(jy1 << 7) + cA]);
        const float b1 = __ldg(&m[(jy1 << 7) + cB]);
        const float c1 = __ldg(&m[(jy1 << 7) + cC]);
        // x-lerp on both rows, both sub-pixels
        const float r0s0 = fmaf(fx0, b0 - a0, a0);
        const float r1s0 = fmaf(fx0, b1 - a1, a1);
        const float r0s1 = fmaf(fx1, c0 - b0, b0);
        const float r1s1 = fmaf(fx1, c1 - b1, b1);
        // y-lerp
        flow0[c] = fmaf(fy, r1s0 - r0s0, r0s0);
        flow1[c] = fmaf(fy, r1s1 - r0s1, r0s1);
    }

    const float2* __restrict__ img2 = (const float2*)image;
    float4 result;

    #pragma unroll
    for (int sub = 0; sub < 2; ++sub) {
        const int x = xh * 2 + sub;
        const float* flow = sub ? flow1 : flow0;

        // --- absolute sample coordinates (flow scaled by (1,2,2)) ---
        const float cz = (float)z + flow[0];
        const float cy = (float)y + 2.0f * flow[1];
        const float cx = (float)x + 2.0f * flow[2];

        const float fz0 = floorf(cz);
        const float fy0 = floorf(cy);
        const float fxx = floorf(cx);
        const int z0 = (int)fz0;
        const int y0 = (int)fy0;
        const int x0 = (int)fxx;
        const float wz = cz - fz0;
        const float wy = cy - fy0;
        const float wx = cx - fxx;

        // --- trilinear gather with zeros padding (branchless) ---
        float accx = 0.0f, accy = 0.0f;
        #pragma unroll
        for (int dz = 0; dz < 2; ++dz) {
            const int zi = z0 + dz;
            const float wzt = dz ? wz : (1.0f - wz);
            const int zc = min(max(zi, 0), DD - 1);
            #pragma unroll
            for (int dy = 0; dy < 2; ++dy) {
                const int yi = y0 + dy;
                const float wyt = dy ? wy : (1.0f - wy);
                const int yc = min(max(yi, 0), HH - 1);
                #pragma unroll
                for (int dx = 0; dx < 2; ++dx) {
                    const int xi = x0 + dx;
                    const float wxt = dx ? wx : (1.0f - wx);
                    const int xc = min(max(xi, 0), WW - 1);
                    const bool valid = ((unsigned)zi < DD) & ((unsigned)yi < HH) & ((unsigned)xi < WW);
                    float w = wzt * wyt * wxt;
                    w = valid ? w : 0.0f;
                    const float2 v = __ldg(&img2[(zc * HH + yc) * WW + xc]);
                    accx = fmaf(w, v.x, accx);
                    accy = fmaf(w, v.y, accy);
                }
            }
        }

        if (sub == 0) { result.x = accx; result.y = accy; }
        else          { result.z = accx; result.w = accy; }
    }

    // Output pixel block for phase p+1:
    // float4 index = ((48 + zp)*256 + y)*128 + xh = tid + COPY_N4
    out4[tid + COPY_N4] = result;
}

extern "C" void kernel_launch(void* const* d_in, const int* in_sizes, int n_in,
                              void* d_out, int out_size)
{
    const float* image = (const float*)d_in[0];
    const float* mvf   = (const float*)d_in[1];

    const int total = COPY_N4 + WARP_N;   // 7,864,320 threads
    mvf_fused_kernel<<<(total + 255) / 256, 256>>>(image, mvf, (float4*)d_out);
}